// round 17
// baseline (speedup 1.0000x reference)
#include <cuda_runtime.h>
#include <cuda_bf16.h>
#include <stdint.h>

#define BATCH 8
#define NN    1024
#define FF    128

// ---------------- scratch (no allocations allowed -> __device__ globals) --------
__device__ uint32_t g_Hbf[(size_t)BATCH * 12 * 8 * 8192];  // 25 MB bf16 B-fragments
__device__ float    g_outacc[(size_t)BATCH * NN * FF];     // 4 MB (self contribution)
__device__ float    g_part[12][(size_t)BATCH * NN * FF];   // 48 MB per-op partials
__device__ float    g_esrc[BATCH * 12 * NN];
__device__ float    g_edst[BATCH * 12 * NN];
__device__ float    g_Htotp[BATCH * 12 * 8 * FF];          // per-rb Htot partials
__device__ uint32_t g_rowbits[(size_t)BATCH * 6 * NN * 32];  // rel 0-2, 6-8 row masks
__device__ uint32_t g_bitsT[(size_t)BATCH * 3 * NN * 32];    // rel 6-8 transposed masks
__device__ uint32_t g_dbits[BATCH * 3 * 32];                 // diag masks (rel 3-5)

// pack two fp32 into bf16x2 word (lo -> low half, hi -> high half)
__device__ __forceinline__ uint32_t pack_bf16x2(float lo, float hi)
{
    uint32_t r;
    asm("cvt.rn.bf16x2.f32 %0, %1, %2;" : "=r"(r) : "f"(hi), "f"(lo));
    return r;
}

// =========== fused bitpack: row masks, transposed masks, diag =====================
__global__ __launch_bounds__(256) void bitpack_kernel(const float* __restrict__ adjs)
{
    const int slab = blockIdx.x, y = blockIdx.y, b = blockIdx.z;
    const int warp = threadIdx.x >> 5, lane = threadIdx.x & 31;

    if (y == 6) {
        if (slab < 3) {                       // diag masks for rel 3..5
            #pragma unroll
            for (int rr = 0; rr < 4; rr++) {
                const int i = rr * 256 + threadIdx.x;
                float v = adjs[(((size_t)(b * 9 + 3 + slab)) * NN + i) * NN + i];
                unsigned m = __ballot_sync(0xffffffffu, v > 0.f);
                if (lane == 0) g_dbits[(b * 3 + slab) * 32 + (i >> 5)] = m;
            }
        }
        return;
    }

    const bool doT = (y >= 3);
    const int rel = doT ? (y + 3) : y;        // y 0-2 -> rel 0-2 ; y 3-5 -> rel 6-8
    __shared__ uint32_t sw[32 * 32];

    #pragma unroll
    for (int rr = 0; rr < 4; rr++) {
        const int row = slab * 32 + warp * 4 + rr;
        const float* rp = adjs + (((size_t)(b * 9 + rel)) * NN + row) * NN;
        uint32_t myw = 0;
        #pragma unroll 4
        for (int it = 0; it < 32; it++) {
            float v = rp[it * 32 + lane];
            unsigned mm = __ballot_sync(0xffffffffu, v > 0.f);
            if (lane == it) myw = mm;
        }
        g_rowbits[(((size_t)(b * 6 + y)) * NN + row) * 32 + lane] = myw;
        if (doT) sw[(warp * 4 + rr) * 32 + lane] = myw;
    }
    if (doT) {
        __syncthreads();
        for (int c = threadIdx.x; c < NN; c += 256) {
            const int word = c >> 5, bit = c & 31;
            uint32_t t = 0;
            #pragma unroll
            for (int r = 0; r < 32; r++)
                t |= ((sw[r * 32 + word] >> bit) & 1u) << r;
            g_bitsT[(((size_t)(b * 3 + (y - 3))) * NN + c) * 32 + slab] = t;
        }
    }
}

// =============================== tf32 GEMM ======================================
// Computes H, writes bf16 MMA-B-fragments directly (hconv fused), per-rb Htot
// partials (no global atomics), and the esrc/edst attention vectors.
__device__ __forceinline__ uint32_t f2tf32(float f)
{
    uint32_t r;
    asm("cvt.rna.tf32.f32 %0, %1;" : "=r"(r) : "f"(f));
    return r;
}

__device__ __forceinline__ void mma_tf32(float4& d, const uint4 a, const uint2 b)
{
    asm volatile(
        "mma.sync.aligned.m16n8k8.row.col.f32.tf32.tf32.f32 "
        "{%0,%1,%2,%3}, {%4,%5,%6,%7}, {%8,%9}, {%0,%1,%2,%3};"
        : "+f"(d.x), "+f"(d.y), "+f"(d.z), "+f"(d.w)
        : "r"(a.x), "r"(a.y), "r"(a.z), "r"(a.w), "r"(b.x), "r"(b.y));
}

#define GEMM_SMEM (32768 * 4)

__global__ __launch_bounds__(512) void gemm_kernel(
    const float* __restrict__ x,
    const float* __restrict__ fc_w,  const float* __restrict__ fc_b,
    const float* __restrict__ fwd_w, const float* __restrict__ fwd_b,
    const float* __restrict__ bwd_w, const float* __restrict__ bwd_b,
    const float* __restrict__ self_w, const float* __restrict__ self_b,
    const float* __restrict__ bias,
    const float* __restrict__ att_w,  const float* __restrict__ att_b,
    const float* __restrict__ fwd_aw, const float* __restrict__ fwd_ab,
    const float* __restrict__ bwd_aw, const float* __restrict__ bwd_ab)
{
    extern __shared__ uint32_t sm[];
    uint32_t* As = sm;
    uint32_t* Ws = sm + 16384;

    const int rb = blockIdx.x, r = blockIdx.y, b = blockIdx.z;
    const int tid = threadIdx.x;

    const float* X = x + (size_t)b * NN * FF + (size_t)rb * 128 * FF;
    const float* Wp; const float* bv; const float* bv2 = nullptr;
    if (r < 6)       { Wp = fc_w  + r * FF * FF;       bv = fc_b  + r * FF; }
    else if (r < 9)  { Wp = fwd_w + (r - 6) * FF * FF; bv = fwd_b + (r - 6) * FF; }
    else if (r < 12) { Wp = bwd_w + (r - 9) * FF * FF; bv = bwd_b + (r - 9) * FF; }
    else             { Wp = self_w; bv = self_b; bv2 = bias; }

    for (int t = tid; t < 4096; t += 512) {
        const int row = t >> 5;
        const int c = (t & 31) << 2;
        float4 v = *(const float4*)(X + (size_t)row * FF + c);
        const int m = row >> 4, lr = row & 15;
        const int s = c >> 3;
        const int reg = (lr >> 3) + ((c & 4) ? 2 : 0);
        uint32_t* base = As + (((m << 4) + s) << 7) + (((lr & 7) << 2) << 2) + reg;
        base[0]  = f2tf32(v.x);
        base[4]  = f2tf32(v.y);
        base[8]  = f2tf32(v.z);
        base[12] = f2tf32(v.w);
    }
    for (int t = tid; t < 4096; t += 512) {
        const int n = t >> 5;
        const int k = (t & 31) << 2;
        float4 v = *(const float4*)(Wp + (size_t)n * FF + k);
        const int nt = n >> 3;
        const int s = k >> 3;
        const int reg = (k & 4) ? 1 : 0;
        uint32_t* base = Ws + (((nt << 4) + s) << 6) + (((n & 7) << 2) << 1) + reg;
        base[0] = f2tf32(v.x);
        base[2] = f2tf32(v.y);
        base[4] = f2tf32(v.z);
        base[6] = f2tf32(v.w);
    }
    __syncthreads();

    const int warp = tid >> 5, lane = tid & 31;
    const int wm = warp >> 2, wn = warp & 3;

    float4 acc[2][4];
    #pragma unroll
    for (int i = 0; i < 2; i++)
        #pragma unroll
        for (int j = 0; j < 4; j++) acc[i][j] = make_float4(0.f, 0.f, 0.f, 0.f);

    #pragma unroll
    for (int s = 0; s < 16; s++) {
        uint4 a[2]; uint2 bb[4];
        #pragma unroll
        for (int i = 0; i < 2; i++)
            a[i] = *(const uint4*)(As + ((((wm * 2 + i) << 4) + s) << 7) + (lane << 2));
        #pragma unroll
        for (int j = 0; j < 4; j++)
            bb[j] = *(const uint2*)(Ws + ((((wn * 4 + j) << 4) + s) << 6) + (lane << 1));
        #pragma unroll
        for (int i = 0; i < 2; i++)
            #pragma unroll
            for (int j = 0; j < 4; j++)
                mma_tf32(acc[i][j], a[i], bb[j]);
    }

    const int g = lane >> 2, t4 = lane & 3;
    float b0[4], b1[4];
    #pragma unroll
    for (int j = 0; j < 4; j++) {
        const int col = (wn * 4 + j) * 8 + 2 * t4;
        b0[j] = bv[col];     b1[j] = bv[col + 1];
        if (bv2) { b0[j] += bv2[col]; b1[j] += bv2[col + 1]; }
    }

    if (r == 12) {
        float* dst = g_outacc + (size_t)b * NN * FF;
        #pragma unroll
        for (int i = 0; i < 2; i++) {
            const int row0 = rb * 128 + (wm * 2 + i) * 16 + g;
            #pragma unroll
            for (int j = 0; j < 4; j++) {
                const int col = (wn * 4 + j) * 8 + 2 * t4;
                float2 lo = make_float2(acc[i][j].x + b0[j], acc[i][j].y + b1[j]);
                float2 hi = make_float2(acc[i][j].z + b0[j], acc[i][j].w + b1[j]);
                *(float2*)(dst + (size_t)row0 * FF + col)       = lo;
                *(float2*)(dst + (size_t)(row0 + 8) * FF + col) = hi;
            }
        }
        return;
    }

    // ---- fused hconv: stage fp32 H tile in smem, emit bf16 B-fragments --------
    {
        __syncthreads();                       // all warps done reading As/Ws
        float* smf = (float*)sm;               // 128 rows x pitch 132 = 16896 floats
        #pragma unroll
        for (int i = 0; i < 2; i++) {
            const int rl_ = (wm * 2 + i) * 16 + g;
            #pragma unroll
            for (int j = 0; j < 4; j++) {
                const int col = (wn * 4 + j) * 8 + 2 * t4;
                *(float2*)(smf + rl_ * 132 + col) =
                    make_float2(acc[i][j].x + b0[j], acc[i][j].y + b1[j]);
                *(float2*)(smf + (rl_ + 8) * 132 + col) =
                    make_float2(acc[i][j].z + b0[j], acc[i][j].w + b1[j]);
            }
        }
        __syncthreads();
        uint32_t* dstf = g_Hbf + ((size_t)(b * 12 + r) * 8 + rb) * 8192;
        #pragma unroll
        for (int it = 0; it < 16; it++) {
            const int o = it * 512 + tid;
            const int rg = o & 1, l2 = (o >> 1) & 31, kt = (o >> 6) & 7, nt = o >> 9;
            const int tt = l2 & 3, g2 = l2 >> 2;
            const int rp = kt * 8 + rg * 4 + tt;    // row pair (2rp, 2rp+1)
            const int f = nt * 8 + g2;
            dstf[o] = pack_bf16x2(smf[2 * rp * 132 + f], smf[(2 * rp + 1) * 132 + f]);
        }
    }

    // ---- Htot per-rb partials via smem reduction (no global atomics) -----------
    {
        __syncthreads();                       // fragment emission done with smf
        float* hsum = (float*)sm;
        if (tid < 128) hsum[tid] = 0.f;
        __syncthreads();
        #pragma unroll
        for (int j = 0; j < 4; j++) {
            float s0 = 0.f, s1 = 0.f;
            #pragma unroll
            for (int i = 0; i < 2; i++) {
                s0 += acc[i][j].x + acc[i][j].z;
                s1 += acc[i][j].y + acc[i][j].w;
            }
            #pragma unroll
            for (int off = 16; off >= 4; off >>= 1) {
                s0 += __shfl_down_sync(0xffffffffu, s0, off);
                s1 += __shfl_down_sync(0xffffffffu, s1, off);
            }
            if (lane < 4) {
                const int col = (wn * 4 + j) * 8 + 2 * lane;
                atomicAdd(&hsum[col], s0);
                atomicAdd(&hsum[col + 1], s1);
            }
        }
        __syncthreads();
        if (tid < 128)
            g_Htotp[((b * 12 + r) * 8 + rb) * FF + tid] = hsum[tid] + 128.f * bv[tid];
    }

    // ---- fused attention e-vectors (esrc/edst) for r<6; r==5 also serves ops 6-11
    if (r < 6) {
        float* es_s = (float*)sm;         // reuse smem (synced inside loop)
        float* ed_s = ((float*)sm) + 128;
        const int nsets = (r == 5) ? 7 : 1;
        for (int set = 0; set < nsets; set++) {
            const int opx = (set == 0) ? r : 5 + set;
            const float* w; float ab;
            if (opx < 6)      { w = att_w  + opx * 2 * FF;       ab = att_b[opx]; }
            else if (opx < 9) { w = fwd_aw + (opx - 6) * 2 * FF; ab = fwd_ab[opx - 6]; }
            else              { w = bwd_aw + (opx - 9) * 2 * FF; ab = bwd_ab[opx - 9]; }
            float c1 = 0.f, c2 = 0.f;
            #pragma unroll
            for (int q = 0; q < 4; q++) {
                float bvv = bv[lane + 32 * q];
                c1 += bvv * w[lane + 32 * q];
                c2 += bvv * w[FF + lane + 32 * q];
            }
            #pragma unroll
            for (int off = 16; off > 0; off >>= 1) {
                c1 += __shfl_xor_sync(0xffffffffu, c1, off);
                c2 += __shfl_xor_sync(0xffffffffu, c2, off);
            }
            c1 += ab;
            __syncthreads();
            if (tid < 128) { es_s[tid] = 0.f; ed_s[tid] = 0.f; }
            __syncthreads();
            #pragma unroll
            for (int i = 0; i < 2; i++) {
                const int rl = (wm * 2 + i) * 16 + g;
                float p1a = 0.f, p2a = 0.f, p1b = 0.f, p2b = 0.f;
                #pragma unroll
                for (int j = 0; j < 4; j++) {
                    const int col = (wn * 4 + j) * 8 + 2 * t4;
                    const float w1a = w[col],      w1b = w[col + 1];
                    const float w2a = w[FF + col], w2b = w[FF + col + 1];
                    p1a += acc[i][j].x * w1a + acc[i][j].y * w1b;
                    p2a += acc[i][j].x * w2a + acc[i][j].y * w2b;
                    p1b += acc[i][j].z * w1a + acc[i][j].w * w1b;
                    p2b += acc[i][j].z * w2a + acc[i][j].w * w2b;
                }
                atomicAdd(&es_s[rl], p1a);     atomicAdd(&ed_s[rl], p2a);
                atomicAdd(&es_s[rl + 8], p1b); atomicAdd(&ed_s[rl + 8], p2b);
            }
            __syncthreads();
            if (tid < 128) {
                g_esrc[(b * 12 + opx) * NN + rb * 128 + tid] = es_s[tid] + c1;
                g_edst[(b * 12 + opx) * NN + rb * 128 + tid] = ed_s[tid] + c2;
            }
        }
    }
}

// ============== sparse-scatter MMA aggregation (double-buffered) ================
__device__ __forceinline__ void mma_bf16(float4& d, const uint4 a, const uint2 b)
{
    asm volatile(
        "mma.sync.aligned.m16n8k16.row.col.f32.bf16.bf16.f32 "
        "{%0,%1,%2,%3}, {%4,%5,%6,%7}, {%8,%9}, {%0,%1,%2,%3};"
        : "+f"(d.x), "+f"(d.y), "+f"(d.z), "+f"(d.w)
        : "r"(a.x), "r"(a.y), "r"(a.z), "r"(a.w), "r"(b.x), "r"(b.y));
}

#define AGG_SMEM (65536)

__global__ __launch_bounds__(512, 2) void agg_kernel()
{
    extern __shared__ uint32_t smd[];       // Aw double buffer: 2 x 8192 words
    __shared__ float wsum_s[128];
    __shared__ float htot_s[128];

    const int rb = blockIdx.x, op = blockIdx.y, b = blockIdx.z;
    const int inst = b * 12 + op;
    const int tid = threadIdx.x;
    const int rl = tid >> 2, wq = tid & 3;     // row-local 0..127, k-word 0..3

    const uint32_t* rowbits = nullptr;
    const uint32_t* dwords = nullptr;
    float scale = 1.0f;
    if (op < 3)      rowbits = g_rowbits + (((size_t)(b * 6 + op)) * NN) * 32;
    else if (op < 6) dwords = g_dbits + (b * 3 + (op - 3)) * 32;
    else if (op < 9) { rowbits = g_rowbits + (((size_t)(b * 6 + op - 3)) * NN) * 32; scale = 0.5f; }
    else             { rowbits = g_bitsT + (((size_t)(b * 3 + op - 9)) * NN) * 32;   scale = 0.5f; }

    const int warp = tid >> 5, lane = tid & 31;
    const int wm = warp >> 2, wn = warp & 3;          // warp tile 32 rows x 32 feats
    const uint32_t* Bg0 = g_Hbf + (size_t)inst * 8 * 8192;

    // sum the 8 per-rb Htot partials into smem (read once per CTA)
    if (tid < 128) {
        float s = 0.f;
        #pragma unroll
        for (int q = 0; q < 8; q++)
            s += g_Htotp[((size_t)inst * 8 + q) * FF + tid];
        htot_s[tid] = s;
        wsum_s[tid] = 0.f;
    }

    // per-thread scatter addressing constants (owned 16 Aw words, disjoint)
    const int mt = rl >> 4, gg = rl & 7, rb0 = (rl >> 3) & 1;
    const uint32_t byteBase = 4u * (uint32_t)(mt * 1024 + gg * 16 + rb0) + wq * 1024u;

    const float es = g_esrc[inst * NN + rb * 128 + rl];
    bool rowActive = true;
    if (dwords) {
        const int row = rb * 128 + rl;
        rowActive = ((__ldg(dwords + (row >> 5)) >> (row & 31)) & 1u) != 0;
    }
    const uint32_t* mask_base = rowbits ? (rowbits + (size_t)(rb * 128 + rl) * 32 + wq)
                                        : nullptr;
    const float* edst_base = g_edst + inst * NN + wq * 32;

    float wsum_local = 0.f;

    // scatter chunk cc into buffer buf (writes only this thread's owned slots)
    auto scatter = [&](int cc, uint32_t* buf) {
        uint32_t mask;
        if (rowbits) mask = __ldg(mask_base + cc * 4);
        else         mask = rowActive ? __ldg(dwords + cc * 4 + wq) : 0u;
        const float* ep = edst_base + cc * 128;
        char* baseB = (char*)buf;
        while (mask) {
            const int kl = __ffs(mask) - 1; mask &= mask - 1;
            float l = es + __ldg(ep + kl);
            l = fmaxf(l, 0.01f * l);
            const float w = __expf(l) - 1.0f;
            wsum_local += w;
            unsigned short hv;
            asm("cvt.rn.bf16.f32 %0, %1;" : "=h"(hv) : "f"(w));
            const uint32_t off = byteBase + (uint32_t)(((kl & 16) << 5) + ((kl & 6) << 3)
                                                       + (kl & 8) + ((kl & 1) << 1));
            *(unsigned short*)(baseB + off) = hv;
        }
    };

    float4 acc[2][4];
    #pragma unroll
    for (int i = 0; i < 2; i++)
        #pragma unroll
        for (int j = 0; j < 4; j++) acc[i][j] = make_float4(0.f, 0.f, 0.f, 0.f);

    // prologue: zero both buffers, scatter chunk 0
    {
        const uint4 z = make_uint4(0u, 0u, 0u, 0u);
        #pragma unroll
        for (int t = 0; t < 4; t++) {
            *(uint4*)(smd + (tid + t * 512) * 4) = z;
            *(uint4*)(smd + 8192 + (tid + t * 512) * 4) = z;
        }
    }
    __syncthreads();
    scatter(0, smd);
    __syncthreads();

    for (int c = 0; c < 8; c++) {
        uint32_t* cur = (c & 1) ? (smd + 8192) : smd;
        uint32_t* nxt = (c & 1) ? smd : (smd + 8192);

        if (c < 7) scatter(c + 1, nxt);    // overlaps with MMAs below

        const uint32_t* Bg = Bg0 + (size_t)c * 8192;
        #pragma unroll
        for (int kt = 0; kt < 8; kt++) {
            uint4 a[2]; uint2 bb[4];
            #pragma unroll
            for (int i = 0; i < 2; i++)
                a[i] = *(const uint4*)(cur + (((wm * 2 + i) * 8 + kt) * 32 + lane) * 4);
            #pragma unroll
            for (int j = 0; j < 4; j++)
                bb[j] = *(const uint2*)(Bg + (((wn * 4 + j) * 8 + kt) * 32 + lane) * 2);
            #pragma unroll
            for (int i = 0; i < 2; i++)
                #pragma unroll
                for (int j = 0; j < 4; j++)
                    mma_bf16(acc[i][j], a[i], bb[j]);
        }
        __syncthreads();                   // scatter(c+1) + MMA(c) complete

        if (c < 6) {                       // re-zero dead buffer for chunk c+2
            const uint4 z = make_uint4(0u, 0u, 0u, 0u);
            #pragma unroll
            for (int t = 0; t < 4; t++)
                *(uint4*)(cur + (tid + t * 512) * 4) = z;
            __syncthreads();
        }
    }

    atomicAdd(&wsum_s[rl], wsum_local);
    __syncthreads();

    // ---- epilogue: (Htot + U) * scale / (1024 + Wsum) ----
    const int g = lane >> 2, t4 = lane & 3;
    float* part = g_part[op] + ((size_t)b * NN) * FF;
    #pragma unroll
    for (int i = 0; i < 2; i++) {
        const int rloc = (wm * 2 + i) * 16 + g;
        const float inv0 = scale / (1024.0f + wsum_s[rloc]);
        const float inv1 = scale / (1024.0f + wsum_s[rloc + 8]);
        const int m0 = rb * 128 + rloc;
        #pragma unroll
        for (int j = 0; j < 4; j++) {
            const int f = (wn * 4 + j) * 8 + t4 * 2;
            const float2 ht = *(const float2*)(htot_s + f);
            float2 lo = make_float2((ht.x + acc[i][j].x) * inv0,
                                    (ht.y + acc[i][j].y) * inv0);
            float2 hi = make_float2((ht.x + acc[i][j].z) * inv1,
                                    (ht.y + acc[i][j].w) * inv1);
            *(float2*)(part + (size_t)m0 * FF + f)       = lo;
            *(float2*)(part + (size_t)(m0 + 8) * FF + f) = hi;
        }
    }
}

// =========================== final reduce + ReLU ================================
__global__ __launch_bounds__(256) void reduce_kernel(float* __restrict__ out)
{
    const int i = blockIdx.x * blockDim.x + threadIdx.x;   // float4 index
    float4 v = ((const float4*)g_outacc)[i];
    #pragma unroll
    for (int op = 0; op < 12; op++) {
        float4 p = ((const float4*)(g_part[op]))[i];
        v.x += p.x; v.y += p.y; v.z += p.z; v.w += p.w;
    }
    v.x = fmaxf(v.x, 0.f); v.y = fmaxf(v.y, 0.f);
    v.z = fmaxf(v.z, 0.f); v.w = fmaxf(v.w, 0.f);
    ((float4*)out)[i] = v;
}

// ================================================================================
extern "C" void kernel_launch(void* const* d_in, const int* in_sizes, int n_in,
                              void* d_out, int out_size)
{
    const float* batch_x    = (const float*)d_in[0];
    const float* batch_adjs = (const float*)d_in[1];
    const float* fc_w       = (const float*)d_in[2];
    const float* fc_b       = (const float*)d_in[3];
    const float* att_w      = (const float*)d_in[4];
    const float* att_b      = (const float*)d_in[5];
    const float* fwd_fc_w   = (const float*)d_in[6];
    const float* fwd_fc_b   = (const float*)d_in[7];
    const float* fwd_att_w  = (const float*)d_in[8];
    const float* fwd_att_b  = (const float*)d_in[9];
    const float* bwd_fc_w   = (const float*)d_in[10];
    const float* bwd_fc_b   = (const float*)d_in[11];
    const float* bwd_att_w  = (const float*)d_in[12];
    const float* bwd_att_b  = (const float*)d_in[13];
    const float* self_w     = (const float*)d_in[14];
    const float* self_b     = (const float*)d_in[15];
    const float* bias       = (const float*)d_in[16];
    float* out = (float*)d_out;

    static cudaStream_t s2;
    static cudaEvent_t evA, evB;
    static bool init_done = false;
    if (!init_done) {
        cudaFuncSetAttribute(gemm_kernel, cudaFuncAttributeMaxDynamicSharedMemorySize, GEMM_SMEM);
        cudaFuncSetAttribute(agg_kernel, cudaFuncAttributeMaxDynamicSharedMemorySize, AGG_SMEM);
        cudaStreamCreateWithFlags(&s2, cudaStreamNonBlocking);
        cudaEventCreateWithFlags(&evA, cudaEventDisableTiming);
        cudaEventCreateWithFlags(&evB, cudaEventDisableTiming);
        init_done = true;
    }

    // fork: bitpack (HBM-bound) runs concurrently with gemm (tensor-bound)
    cudaEventRecord(evA, 0);
    cudaStreamWaitEvent(s2, evA, 0);
    bitpack_kernel<<<dim3(32, 7, 8), 256, 0, s2>>>(batch_adjs);
    cudaEventRecord(evB, s2);

    gemm_kernel<<<dim3(8, 13, 8), 512, GEMM_SMEM>>>(batch_x, fc_w, fc_b,
                                                    fwd_fc_w, fwd_fc_b,
                                                    bwd_fc_w, bwd_fc_b,
                                                    self_w, self_b, bias,
                                                    att_w, att_b, fwd_att_w,
                                                    fwd_att_b, bwd_att_w, bwd_att_b);

    // join: agg needs both masks (bitpack) and fragments/vectors (gemm)
    cudaStreamWaitEvent(0, evB, 0);
    agg_kernel<<<dim3(8, 12, 8), 512, AGG_SMEM>>>();
    reduce_kernel<<<1024, 256>>>(out);
}